// round 12
// baseline (speedup 1.0000x reference)
#include <cuda_runtime.h>
#include <cuda_bf16.h>
#include <cstdint>
#include <float.h>

#define DINL __device__ __forceinline__

// ---------------- scratch (__device__ globals; no allocs allowed) ----------------
__device__ __nv_bfloat16 g_B[128 * 512];        // W^T bf16, [e][k] k-contiguous
__device__ float g_WT[128 * 512];               // W^T fp32, [e][k] (for exact recompute)
__device__ float g_cand[1024 * 128 * 10];       // per-(128-row chunk,e): 5 max + 5 min
__device__ int   g_candIdx[1024 * 128 * 10];    // row-in-batch indices for the above
__device__ float g_pooled[32 * 128];

// ---------------- helpers ----------------
DINL uint32_t smem_u32(const void* p) {
    uint32_t a;
    asm("{ .reg .u64 t; cvta.to.shared.u64 t, %1; cvt.u32.u64 %0, t; }" : "=r"(a) : "l"(p));
    return a;
}

DINL void ldmatrix4(uint32_t& r0, uint32_t& r1, uint32_t& r2, uint32_t& r3, uint32_t addr) {
    asm volatile("ldmatrix.sync.aligned.m8n8.x4.shared.b16 {%0,%1,%2,%3}, [%4];"
                 : "=r"(r0), "=r"(r1), "=r"(r2), "=r"(r3) : "r"(addr));
}

DINL void mma16816(float* c, uint32_t a0, uint32_t a1, uint32_t a2, uint32_t a3,
                   uint32_t b0, uint32_t b1) {
    asm volatile(
        "mma.sync.aligned.m16n8k16.row.col.f32.bf16.bf16.f32 "
        "{%0,%1,%2,%3}, {%4,%5,%6,%7}, {%8,%9}, {%0,%1,%2,%3};"
        : "+f"(c[0]), "+f"(c[1]), "+f"(c[2]), "+f"(c[3])
        : "r"(a0), "r"(a1), "r"(a2), "r"(a3), "r"(b0), "r"(b1));
}

DINL void cp_async16(uint32_t dst, const void* src) {
    asm volatile("cp.async.cg.shared.global [%0], [%1], 16;" :: "r"(dst), "l"(src) : "memory");
}
DINL void cp_commit() { asm volatile("cp.async.commit_group;" ::: "memory"); }
DINL void cp_wait1()  { asm volatile("cp.async.wait_group 1;" ::: "memory"); }
DINL void cp_wait2()  { asm volatile("cp.async.wait_group 2;" ::: "memory"); }

DINL uint32_t packbf(float x, float y) {
    __nv_bfloat162 p = __floats2bfloat162_rn(x, y);
    return *(uint32_t*)&p;
}

// sorted-5 insertion, max side (v0>=..>=v4)
DINL void ins5max(float v, int i, float& v0, int& i0, float& v1, int& i1,
                  float& v2, int& i2, float& v3, int& i3, float& v4, int& i4) {
    if (v > v4) {
        if (v > v2) {
            if (v > v0)      { v4=v3;i4=i3; v3=v2;i3=i2; v2=v1;i2=i1; v1=v0;i1=i0; v0=v;i0=i; }
            else if (v > v1) { v4=v3;i4=i3; v3=v2;i3=i2; v2=v1;i2=i1; v1=v;i1=i; }
            else             { v4=v3;i4=i3; v3=v2;i3=i2; v2=v;i2=i; }
        } else {
            if (v > v3)      { v4=v3;i4=i3; v3=v;i3=i; }
            else             { v4=v;i4=i; }
        }
    }
}
// sorted-5 insertion, min side (v0<=..<=v4)
DINL void ins5min(float v, int i, float& v0, int& i0, float& v1, int& i1,
                  float& v2, int& i2, float& v3, int& i3, float& v4, int& i4) {
    if (v < v4) {
        if (v < v2) {
            if (v < v0)      { v4=v3;i4=i3; v3=v2;i3=i2; v2=v1;i2=i1; v1=v0;i1=i0; v0=v;i0=i; }
            else if (v < v1) { v4=v3;i4=i3; v3=v2;i3=i2; v2=v1;i2=i1; v1=v;i1=i; }
            else             { v4=v3;i4=i3; v3=v2;i3=i2; v2=v;i2=i; }
        } else {
            if (v < v3)      { v4=v3;i4=i3; v3=v;i3=i; }
            else             { v4=v;i4=i; }
        }
    }
}

// ---------------- kernel 1: W [512,128] fp32 -> g_B bf16 + g_WT fp32 ([e][k]) ----------------
__global__ void prep_B_kernel(const float* __restrict__ W) {
    int idx = blockIdx.x * 256 + threadIdx.x;   // 65536
    int k = idx >> 7, e = idx & 127;
    float v = W[idx];
    g_B[e * 512 + k] = __float2bfloat16(v);
    g_WT[e * 512 + k] = v;
}

// ---------------- kernel 2: barrier-free warp-striped bf16 HMMA GEMM + top5/bot5 ----------------
// CTA: 256 rows x 128 e, 512 threads = 16 warps; warp w owns rows w*16..w*16+15 (full 128 e).
// B (128KB bf16, swizzled) resident in smem; per-warp private 2-stage cp.async A staging.
// NO __syncthreads in the K-loop: warps free-run on wait_group/__syncwarp only.
static constexpr int OFF_B = 0;
static constexpr int B_BYTES = 131072;              // 128 e x 1KB rows, (c16 ^ (e&7)) swizzle
static constexpr int A_RSTRIDE = 160;               // 128B fp32 row + 32B pad (bank-clean)
static constexpr int A_STAGE = 16 * A_RSTRIDE;      // 2560 per warp per stage
static constexpr int A_PER_WARP = 2 * A_STAGE;      // 5120
static constexpr int OFF_A = B_BYTES;               // A region also reused as epilogue fb
static constexpr int SM_BYTES = OFF_A + 16 * A_PER_WARP;   // 212992

__global__ void __launch_bounds__(512, 1) gemm_pool_kernel(const float* __restrict__ x) {
    extern __shared__ __align__(128) char smem[];
    const uint32_t sb = smem_u32(smem);
    const int tid = threadIdx.x, lane = tid & 31, wid = tid >> 5;   // wid 0..15
    const int cta = blockIdx.x;
    const float* xg = x + (size_t)cta * 256 * 512;
    const int wrow = wid * 16;                       // warp's first row (0..240)
    const uint32_t a32base = sb + OFF_A + wid * A_PER_WARP;

    // ---- B resident: 8192 x 16B cp.async, swizzled (c16 ^ (e&7)) within 1KB rows ----
    #pragma unroll
    for (int i = 0; i < 16; i++) {
        int u = tid + 512 * i;
        int e = u >> 6, c = u & 63;
        uint32_t dst = sb + OFF_B + (uint32_t)(e * 1024 + ((c ^ (e & 7)) << 4));
        cp_async16(dst, (const char*)g_B + (size_t)u * 16);
    }
    cp_commit();

    // ---- warp-private A chunk staging: 16 rows x 32 k fp32, row stride 160B ----
    #define ISSUE_A(kc, st)                                                         \
    {                                                                               \
        _Pragma("unroll")                                                           \
        for (int i = 0; i < 4; i++) {                                               \
            int u = i * 32 + lane;                                                  \
            int r = u >> 3, c = u & 7;                                              \
            cp_async16(a32base + (st) * A_STAGE + r * A_RSTRIDE + c * 16,           \
                       xg + (size_t)(wrow + r) * 512 + (kc) * 32 + c * 4);          \
        }                                                                           \
        cp_commit();                                                                \
    }

    ISSUE_A(0, 0);
    ISSUE_A(1, 1);
    cp_wait2();          // B complete (A groups 0,1 may be pending)
    __syncthreads();     // publish B to all warps — the ONLY CTA barrier before epilogue

    // ---- accumulators: warp tile 16(m) x 128(n) = 64 regs ----
    float acc[16][4];
    #pragma unroll
    for (int i = 0; i < 16; i++)
        #pragma unroll
        for (int j = 0; j < 4; j++) acc[i][j] = 0.f;

    for (int kc = 0; kc < 16; kc++) {
        cp_wait1();          // own chunk kc complete (only kc+1 pending)
        __syncwarp();        // publish this warp's staged A across its lanes

        const char* Ab = smem + OFF_A + wid * A_PER_WARP + (kc & 1) * A_STAGE;
        const char* ab0 = Ab + (lane >> 2) * A_RSTRIDE + (lane & 3) * 8;

        #pragma unroll
        for (int ks = 0; ks < 2; ks++) {
            // A fragment: canonical m16n8k16 row-major mapping, fp32 -> bf16 pack
            const char* ap = ab0 + ks * 64;
            float2 p0 = *(const float2*)(ap);
            float2 p1 = *(const float2*)(ap + 8 * A_RSTRIDE);
            float2 p2 = *(const float2*)(ap + 32);
            float2 p3 = *(const float2*)(ap + 8 * A_RSTRIDE + 32);
            uint32_t a0 = packbf(p0.x, p0.y), a1 = packbf(p1.x, p1.y);
            uint32_t a2 = packbf(p2.x, p2.y), a3 = packbf(p3.x, p3.y);

            const int c16 = kc * 4 + ks * 2 + (lane >> 4);
            #pragma unroll
            for (int nb = 0; nb < 8; nb++) {
                int el = nb * 16 + (lane & 15);
                uint32_t off = (uint32_t)(el * 1024 + ((c16 ^ (el & 7)) << 4));
                uint32_t b0, b1, b2, b3;
                ldmatrix4(b0, b1, b2, b3, sb + OFF_B + off);
                mma16816(acc[nb * 2], a0, a1, a2, a3, b0, b2);
                mma16816(acc[nb * 2 + 1], a0, a1, a2, a3, b1, b3);
            }
        }

        __syncwarp();        // all lanes done reading stage (kc&1) before refill
        if (kc + 2 < 16) { ISSUE_A(kc + 2, kc & 1); }
        else             { cp_commit(); }   // empty group keeps wait accounting exact
    }

    __syncthreads();   // everyone done; A region reusable as fb

    // ---- epilogue: two 128-row halves through fb[128][132] (reused A region) ----
    float* fb = (float*)(smem + OFF_A);
    for (int half = 0; half < 2; half++) {
        if ((wid >> 3) == half) {
            int r0 = (wid & 7) * 16 + (lane >> 2);
            #pragma unroll
            for (int nb = 0; nb < 8; nb++)
                #pragma unroll
                for (int h = 0; h < 2; h++) {
                    int c = nb * 16 + h * 8 + (lane & 3) * 2;
                    float* a4 = acc[nb * 2 + h];
                    fb[r0 * 132 + c] = a4[0];
                    fb[r0 * 132 + c + 1] = a4[1];
                    fb[(r0 + 8) * 132 + c] = a4[2];
                    fb[(r0 + 8) * 132 + c + 1] = a4[3];
                }
        }
        __syncthreads();
        if (tid < 128) {
            const int e = tid;
            const int chunkIdx = cta * 2 + half;        // 128-row chunk id (0..1023)
            float t0=-FLT_MAX,t1=-FLT_MAX,t2=-FLT_MAX,t3=-FLT_MAX,t4=-FLT_MAX;
            int   a0i=0,a1i=0,a2i=0,a3i=0,a4i=0;
            float u0=FLT_MAX,u1=FLT_MAX,u2=FLT_MAX,u3=FLT_MAX,u4=FLT_MAX;
            int   b0i=0,b1i=0,b2i=0,b3i=0,b4i=0;
            const int rbase = (chunkIdx & 31) * 128;    // row-in-batch offset
            for (int r = 0; r < 128; r++) {
                float v = fb[r * 132 + e];
                ins5max(v, rbase + r, t0,a0i, t1,a1i, t2,a2i, t3,a3i, t4,a4i);
                ins5min(v, rbase + r, u0,b0i, u1,b1i, u2,b2i, u3,b3i, u4,b4i);
            }
            size_t o = ((size_t)chunkIdx * 128 + e) * 10;
            g_cand[o+0]=t0; g_cand[o+1]=t1; g_cand[o+2]=t2; g_cand[o+3]=t3; g_cand[o+4]=t4;
            g_cand[o+5]=u0; g_cand[o+6]=u1; g_cand[o+7]=u2; g_cand[o+8]=u3; g_cand[o+9]=u4;
            g_candIdx[o+0]=a0i; g_candIdx[o+1]=a1i; g_candIdx[o+2]=a2i; g_candIdx[o+3]=a3i; g_candIdx[o+4]=a4i;
            g_candIdx[o+5]=b0i; g_candIdx[o+6]=b1i; g_candIdx[o+7]=b2i; g_candIdx[o+8]=b3i; g_candIdx[o+9]=b4i;
        }
        __syncthreads();
    }
    #undef ISSUE_A
}

// ---------------- kernel 3: merge chunks, exact fp32 recompute, pool ----------------
// grid = 4096 (b*128+e), block = 64 (warp0: max side, warp1: min side)
__global__ void merge_pool_kernel(const float* __restrict__ x) {
    const int blk = blockIdx.x;
    const int b = blk >> 7, e = blk & 127;
    const int tid = threadIdx.x, lane = tid & 31, w = tid >> 5;
    __shared__ int s_idx[10];
    __shared__ float s_exact[10];
    __shared__ float s_wcol[512];

    {
        const float4* wt = (const float4*)(g_WT + (size_t)e * 512);
        ((float4*)s_wcol)[tid] = wt[tid];
        ((float4*)s_wcol)[tid + 64] = wt[tid + 64];
    }

    // phase 1: each lane owns one of 32 chunks; warp-merge sorted-5 lists -> global top5
    {
        size_t base = (((size_t)(b * 32 + lane)) * 128 + e) * 10 + (w ? 5 : 0);
        float v0, v1, v2, v3, v4;
        int j0, j1, j2, j3, j4;
        v0 = g_cand[base+0]; v1 = g_cand[base+1]; v2 = g_cand[base+2];
        v3 = g_cand[base+3]; v4 = g_cand[base+4];
        j0 = g_candIdx[base+0]; j1 = g_candIdx[base+1]; j2 = g_candIdx[base+2];
        j3 = g_candIdx[base+3]; j4 = g_candIdx[base+4];
        if (w) { v0 = -v0; v1 = -v1; v2 = -v2; v3 = -v3; v4 = -v4; }

        #pragma unroll
        for (int r = 0; r < 5; r++) {
            float cur = v0;
            float m = cur;
            #pragma unroll
            for (int s = 16; s; s >>= 1) m = fmaxf(m, __shfl_xor_sync(0xffffffffu, m, s));
            unsigned ball = __ballot_sync(0xffffffffu, cur == m);
            int win = __ffs(ball) - 1;
            int widx = __shfl_sync(0xffffffffu, j0, win);
            if (lane == 0) s_idx[w * 5 + r] = widx;
            if (lane == win) { v0=v1; j0=j1; v1=v2; j1=j2; v2=v3; j2=j3; v3=v4; j3=j4; v4=-FLT_MAX; }
        }
    }
    __syncthreads();

    // phase 2: exact fp32 dot for each candidate
    for (int c = 0; c < 5; c++) {
        int idx = s_idx[w * 5 + c];
        const float* xr = x + ((size_t)b * 4096 + idx) * 512;
        float s = 0.f;
        #pragma unroll
        for (int k = lane; k < 512; k += 32) s = fmaf(xr[k], s_wcol[k], s);
        #pragma unroll
        for (int sh = 16; sh; sh >>= 1) s += __shfl_xor_sync(0xffffffffu, s, sh);
        if (lane == 0) s_exact[w * 5 + c] = s;
    }
    __syncthreads();

    // phase 3: exact top3 + bottom3
    if (tid == 0) {
        float mx[5], mn[5];
        #pragma unroll
        for (int i = 0; i < 5; i++) { mx[i] = s_exact[i]; mn[i] = s_exact[5 + i]; }
        float pmax = 0.f, pmin = 0.f;
        #pragma unroll
        for (int pick = 0; pick < 3; pick++) {
            int bi = 0;
            #pragma unroll
            for (int i = 1; i < 5; i++) if (mx[i] > mx[bi]) bi = i;
            pmax += mx[bi]; mx[bi] = -FLT_MAX;
            int si = 0;
            #pragma unroll
            for (int i = 1; i < 5; i++) if (mn[i] < mn[si]) si = i;
            pmin += mn[si]; mn[si] = FLT_MAX;
        }
        g_pooled[b * 128 + e] = pmax + pmin;
    }
}

// ---------------- kernel 4: L2 normalize ----------------
__global__ void normalize_kernel(float* __restrict__ out) {
    const int b = blockIdx.x, e = threadIdx.x;
    float p = g_pooled[b * 128 + e];
    __shared__ float sq[128];
    sq[e] = p * p;
    __syncthreads();
    for (int s = 64; s; s >>= 1) {
        if (e < s) sq[e] += sq[e + s];
        __syncthreads();
    }
    out[b * 128 + e] = p * rsqrtf(fmaxf(sq[0], 1e-12f));
}

// ---------------- launch ----------------
extern "C" void kernel_launch(void* const* d_in, const int* in_sizes, int n_in,
                              void* d_out, int out_size) {
    (void)in_sizes; (void)n_in; (void)out_size;
    const float* x = (const float*)d_in[0];   // [32,64,64,512] fp32
    const float* W = (const float*)d_in[1];   // [512,128] fp32
    float* out = (float*)d_out;               // [32,128] fp32

    cudaFuncSetAttribute(gemm_pool_kernel,
                         cudaFuncAttributeMaxDynamicSharedMemorySize, SM_BYTES);

    prep_B_kernel<<<256, 256>>>(W);
    gemm_pool_kernel<<<512, 512, SM_BYTES>>>(x);
    merge_pool_kernel<<<4096, 64>>>(x);
    normalize_kernel<<<32, 128>>>(out);
}